// round 8
// baseline (speedup 1.0000x reference)
#include <cuda_runtime.h>
#include <cstdint>

#define N_   4
#define L_   4096
#define H_   8
#define D_   64
#define NH   32
#define EPSF 1e-6f

#define P1_CHUNKS 32
#define P1_LC (L_ / P1_CHUNKS)   // 128 tokens per pass1 CTA
#define P1_T  32                 // tokens per smem tile
#define P1_NT (P1_LC / P1_T)     // 4 tiles
#define NPART P1_CHUNKS

#define TL2 128                  // tokens per pass2 CTA
#define STR 68                   // padded row stride: 16B-aligned rows, conflict-free fragment reads

// Scratch (allocation-free rule: device globals)
__device__ float g_KVp[NH][NPART][D_ * D_];
__device__ float g_KSp[NH][NPART][D_];
__device__ float g_KV[NH][D_ * D_];
__device__ float g_KS[NH][D_];

__device__ __forceinline__ float fmap(float x) {      // elu(x)+1
    return x > 0.f ? x + 1.f : __expf(x);
}
__device__ __forceinline__ float totf32(float x) {    // round-to-nearest tf32
    uint32_t u;
    asm("cvt.rna.tf32.f32 %0, %1;" : "=r"(u) : "f"(x));
    return __uint_as_float(u);
}
__device__ __forceinline__ float ffrag(float x) { return totf32(fmap(x)); }

__device__ __forceinline__ void cp16(void* smem_dst, const void* gmem_src) {
    uint32_t d = (uint32_t)__cvta_generic_to_shared(smem_dst);
    asm volatile("cp.async.cg.shared.global [%0], [%1], 16;\n" :: "r"(d), "l"(gmem_src));
}
__device__ __forceinline__ void cp_commit() {
    asm volatile("cp.async.commit_group;\n");
}
template <int N>
__device__ __forceinline__ void cp_wait() {
    asm volatile("cp.async.wait_group %0;\n" :: "n"(N));
}

__device__ __forceinline__ void mma_tf32(float* c,
                                         uint32_t a0, uint32_t a1, uint32_t a2, uint32_t a3,
                                         uint32_t b0, uint32_t b1) {
    asm volatile("mma.sync.aligned.m16n8k8.row.col.f32.tf32.tf32.f32 "
                 "{%0,%1,%2,%3}, {%4,%5,%6,%7}, {%8,%9}, {%0,%1,%2,%3};\n"
                 : "+f"(c[0]), "+f"(c[1]), "+f"(c[2]), "+f"(c[3])
                 : "r"(a0), "r"(a1), "r"(a2), "r"(a3), "r"(b0), "r"(b1));
}

// ───────────────────────── Pass 1: KV[d][m] = Σ_l f(k)[l,d]·v[l,m], Ksum[d] = Σ_l f(k)[l,d]
// Grid (NH, 32), 256 threads. Warp w: d-tile (w>>1)*16, m-half (w&1)*32.
// Register-staged double buffer: LDG tile i+1 into regs BEFORE MMA(i);
// convert ONCE in regs; single STS; ONE barrier per tile. MMA loop is pure LDS+MMA.
struct P1Smem {
    float ks[2][P1_T][STR];
    float vs[2][P1_T][STR];
};
#define SMEM1 ((int)sizeof(P1Smem))

__global__ __launch_bounds__(256) void pass1(const float* __restrict__ keys,
                                             const float* __restrict__ values) {
    extern __shared__ char smraw[];
    P1Smem& sm = *reinterpret_cast<P1Smem*>(smraw);

    const int nh = blockIdx.x, chunk = blockIdx.y;
    const int n = nh >> 3, h = nh & 7;
    const int tid = threadIdx.x;
    const int w = tid >> 5, lane = tid & 31;
    const int gid = lane >> 2, tig = lane & 3;
    const int d0 = (w >> 1) * 16;
    const int c0 = (w & 1) * 32;

    const float* kb = keys   + ((size_t)(n * L_) * H_ + h) * D_;
    const float* vb = values + ((size_t)(n * L_) * H_ + h) * D_;
    const int l0 = chunk * P1_LC;

    const int t0 = tid >> 4, q40 = (tid & 15) * 4;
    const int t1 = t0 + 16;

    float4 rk0, rk1, rv0, rv1;   // staging registers

    auto ldg = [&](int it) {
        const int lb = l0 + it * P1_T;
        rk0 = *(const float4*)(kb + (size_t)(lb + t0) * (H_ * D_) + q40);
        rv0 = *(const float4*)(vb + (size_t)(lb + t0) * (H_ * D_) + q40);
        rk1 = *(const float4*)(kb + (size_t)(lb + t1) * (H_ * D_) + q40);
        rv1 = *(const float4*)(vb + (size_t)(lb + t1) * (H_ * D_) + q40);
    };
    auto cvst = [&](int b) {
        rk0.x = ffrag(rk0.x); rk0.y = ffrag(rk0.y); rk0.z = ffrag(rk0.z); rk0.w = ffrag(rk0.w);
        rk1.x = ffrag(rk1.x); rk1.y = ffrag(rk1.y); rk1.z = ffrag(rk1.z); rk1.w = ffrag(rk1.w);
        rv0.x = totf32(rv0.x); rv0.y = totf32(rv0.y); rv0.z = totf32(rv0.z); rv0.w = totf32(rv0.w);
        rv1.x = totf32(rv1.x); rv1.y = totf32(rv1.y); rv1.z = totf32(rv1.z); rv1.w = totf32(rv1.w);
        *(float4*)&sm.ks[b][t0][q40] = rk0;
        *(float4*)&sm.ks[b][t1][q40] = rk1;
        *(float4*)&sm.vs[b][t0][q40] = rv0;
        *(float4*)&sm.vs[b][t1][q40] = rv1;
    };

    float acc[4][4] = {};
    float s_lo = 0.f, s_hi = 0.f;

    ldg(0);
    cvst(0);

    #pragma unroll
    for (int it = 0; it < P1_NT; ++it) {
        if (it + 1 < P1_NT) ldg(it + 1);   // LDGs in flight across barrier + MMA
        __syncthreads();                    // buf(it&1) writes visible; last reads of buf((it+1)&1) done

        const float (*ksb)[STR] = sm.ks[it & 1];
        const float (*vsb)[STR] = sm.vs[it & 1];

        #pragma unroll
        for (int kk = 0; kk < P1_T; kk += 8) {
            float a0f = ksb[kk + tig    ][d0 + gid    ];
            float a1f = ksb[kk + tig    ][d0 + gid + 8];
            float a2f = ksb[kk + tig + 4][d0 + gid    ];
            float a3f = ksb[kk + tig + 4][d0 + gid + 8];
            s_lo += a0f + a2f;
            s_hi += a1f + a3f;
            uint32_t a0 = __float_as_uint(a0f), a1 = __float_as_uint(a1f);
            uint32_t a2 = __float_as_uint(a2f), a3 = __float_as_uint(a3f);
            #pragma unroll
            for (int j = 0; j < 4; ++j) {
                uint32_t b0 = __float_as_uint(vsb[kk + tig    ][c0 + j * 8 + gid]);
                uint32_t b1 = __float_as_uint(vsb[kk + tig + 4][c0 + j * 8 + gid]);
                mma_tf32(acc[j], a0, a1, a2, a3, b0, b1);
            }
        }

        if (it + 1 < P1_NT) cvst((it + 1) & 1);   // safe: that buffer's readers passed barrier(it)
    }

    s_lo += __shfl_xor_sync(0xffffffffu, s_lo, 1);
    s_lo += __shfl_xor_sync(0xffffffffu, s_lo, 2);
    s_hi += __shfl_xor_sync(0xffffffffu, s_hi, 1);
    s_hi += __shfl_xor_sync(0xffffffffu, s_hi, 2);

    if (c0 == 0 && tig == 0) {
        g_KSp[nh][chunk][d0 + gid]     = s_lo;
        g_KSp[nh][chunk][d0 + gid + 8] = s_hi;
    }
    float* kv = g_KVp[nh][chunk];
    #pragma unroll
    for (int j = 0; j < 4; ++j) {
        int col = c0 + j * 8 + tig * 2;
        *(float2*)&kv[(d0 + gid    ) * D_ + col] = make_float2(acc[j][0], acc[j][1]);
        *(float2*)&kv[(d0 + gid + 8) * D_ + col] = make_float2(acc[j][2], acc[j][3]);
    }
}

// ───────────────────────── Reduce: sum 32 partials; pre-convert KV to tf32 for pass2
__global__ __launch_bounds__(256) void reduce_kernel() {
    if (blockIdx.x < 128) {
        int base = blockIdx.x * 256 + threadIdx.x;   // float4 index into [NH][4096]
        int nh = base >> 10;
        int e  = base & 1023;
        float4 s = make_float4(0.f, 0.f, 0.f, 0.f);
        #pragma unroll 8
        for (int p = 0; p < NPART; ++p) {
            float4 v = ((const float4*)g_KVp[nh][p])[e];
            s.x += v.x; s.y += v.y; s.z += v.z; s.w += v.w;
        }
        s.x = totf32(s.x); s.y = totf32(s.y); s.z = totf32(s.z); s.w = totf32(s.w);
        ((float4*)g_KV[nh])[e] = s;
    } else {
        for (int i = threadIdx.x; i < NH * D_ / 4; i += 256) {
            int nh = i >> 4;
            int e  = i & 15;
            float4 s = make_float4(0.f, 0.f, 0.f, 0.f);
            #pragma unroll 8
            for (int p = 0; p < NPART; ++p) {
                float4 v = ((const float4*)g_KSp[nh][p])[e];
                s.x += v.x; s.y += v.y; s.z += v.z; s.w += v.w;
            }
            ((float4*)g_KS[nh])[e] = s;
        }
    }
}

// ───────────────────────── Pass 2: out[l][m] = z_l · Σ_d f(q)[l,d]·KV[d][m]
// Grid (NH, 32), 512 threads. q: LDG.128→ffrag in regs→STS (convert once, no round-trip),
// overlapped with the KV cp.async. MMA loop is pure LDS+MMA.
struct P2Smem {
    float kv[D_][STR];
    float q[TL2][STR];
    float ks[D_];
};
#define SMEM2 ((int)sizeof(P2Smem))

__global__ __launch_bounds__(512) void pass2(const float* __restrict__ queries,
                                             float* __restrict__ out) {
    extern __shared__ char smraw[];
    P2Smem& sm = *reinterpret_cast<P2Smem*>(smraw);

    const int nh = blockIdx.x, tile = blockIdx.y;
    const int n = nh >> 3, h = nh & 7;
    const int tid = threadIdx.x;
    const int w = tid >> 5, lane = tid & 31;
    const int gid = lane >> 2, tig = lane & 3;
    const int l0 = tile * TL2;

    // q: 4 LDG.128 per thread, back-to-back (max MLP)
    const float* qb = queries + ((size_t)(n * L_) * H_ + h) * D_;
    float4 rq[4];
    #pragma unroll
    for (int r = 0; r < 4; ++r) {
        int f = r * 512 + tid;
        int t = f >> 4, c = (f & 15) * 4;
        rq[r] = *(const float4*)(qb + (size_t)(l0 + t) * (H_ * D_) + c);
    }
    // KV tile (L2-resident, already tf32) via cp.async — in flight during q convert
    #pragma unroll
    for (int r = 0; r < 2; ++r) {
        int f = r * 512 + tid;
        int dd = f >> 4, c = (f & 15) * 4;
        cp16(&sm.kv[dd][c], (const char*)g_KV[nh] + (size_t)f * 16);
    }
    if (tid < D_) sm.ks[tid] = g_KS[nh][tid];
    cp_commit();

    // convert q once in registers, store
    #pragma unroll
    for (int r = 0; r < 4; ++r) {
        int f = r * 512 + tid;
        int t = f >> 4, c = (f & 15) * 4;
        rq[r].x = ffrag(rq[r].x); rq[r].y = ffrag(rq[r].y);
        rq[r].z = ffrag(rq[r].z); rq[r].w = ffrag(rq[r].w);
        *(float4*)&sm.q[t][c] = rq[r];
    }
    cp_wait<0>();
    __syncthreads();

    const int lb = (w >> 1) * 16;
    const int c0 = (w & 1) * 32;
    float acc[4][4] = {};
    float s_lo = 0.f, s_hi = 0.f;

    #pragma unroll
    for (int kk = 0; kk < D_; kk += 8) {
        float ka = sm.ks[kk + tig], kc = sm.ks[kk + tig + 4];
        float a0f = sm.q[lb + gid    ][kk + tig    ];
        float a1f = sm.q[lb + gid + 8][kk + tig    ];
        float a2f = sm.q[lb + gid    ][kk + tig + 4];
        float a3f = sm.q[lb + gid + 8][kk + tig + 4];
        s_lo += a0f * ka + a2f * kc;
        s_hi += a1f * ka + a3f * kc;
        uint32_t a0 = __float_as_uint(a0f), a1 = __float_as_uint(a1f);
        uint32_t a2 = __float_as_uint(a2f), a3 = __float_as_uint(a3f);
        #pragma unroll
        for (int j = 0; j < 4; ++j) {
            uint32_t b0 = __float_as_uint(sm.kv[kk + tig    ][c0 + j * 8 + gid]);
            uint32_t b1 = __float_as_uint(sm.kv[kk + tig + 4][c0 + j * 8 + gid]);
            mma_tf32(acc[j], a0, a1, a2, a3, b0, b1);
        }
    }

    s_lo += __shfl_xor_sync(0xffffffffu, s_lo, 1);
    s_lo += __shfl_xor_sync(0xffffffffu, s_lo, 2);
    s_hi += __shfl_xor_sync(0xffffffffu, s_hi, 1);
    s_hi += __shfl_xor_sync(0xffffffffu, s_hi, 2);
    const float z_lo = 1.f / (s_lo + EPSF);
    const float z_hi = 1.f / (s_hi + EPSF);

    float* ob_lo = out + (((size_t)(n * L_) + l0 + lb + gid    ) * H_ + h) * D_ + c0;
    float* ob_hi = out + (((size_t)(n * L_) + l0 + lb + gid + 8) * H_ + h) * D_ + c0;
    #pragma unroll
    for (int j = 0; j < 4; ++j) {
        int col = j * 8 + tig * 2;
        *(float2*)(ob_lo + col) = make_float2(acc[j][0] * z_lo, acc[j][1] * z_lo);
        *(float2*)(ob_hi + col) = make_float2(acc[j][2] * z_hi, acc[j][3] * z_hi);
    }
}

extern "C" void kernel_launch(void* const* d_in, const int* in_sizes, int n_in,
                              void* d_out, int out_size) {
    const float* q = (const float*)d_in[0];
    const float* k = (const float*)d_in[1];
    const float* v = (const float*)d_in[2];
    float* out = (float*)d_out;
    (void)in_sizes; (void)n_in; (void)out_size;

    // Idempotent, not stream ops — safe under graph capture.
    cudaFuncSetAttribute(pass1, cudaFuncAttributeMaxDynamicSharedMemorySize, SMEM1);
    cudaFuncSetAttribute(pass2, cudaFuncAttributeMaxDynamicSharedMemorySize, SMEM2);

    pass1<<<dim3(NH, P1_CHUNKS), 256, SMEM1>>>(k, v);
    reduce_kernel<<<129, 256>>>();
    pass2<<<dim3(NH, L_ / TL2), 512, SMEM2>>>(q, out);
}

// round 9
// speedup vs baseline: 1.2188x; 1.2188x over previous
#include <cuda_runtime.h>
#include <cstdint>

#define N_   4
#define L_   4096
#define H_   8
#define D_   64
#define NH   32
#define EPSF 1e-6f

#define P1_CHUNKS 32
#define P1_LC (L_ / P1_CHUNKS)   // 128 tokens per pass1 CTA
#define P1_T  32                 // tokens per smem tile
#define P1_NT (P1_LC / P1_T)     // 4 tiles, 2-stage cp.async pipeline
#define NPART P1_CHUNKS

#define TL2 128                  // tokens per pass2 CTA
#define STR 68                   // padded row stride: 16B-aligned rows, ≤2-way conflicts on fragment reads

// Scratch (allocation-free rule: device globals)
__device__ float g_KVp[NH][NPART][D_ * D_];
__device__ float g_KSp[NH][NPART][D_];
__device__ float g_KV[NH][D_ * D_];
__device__ float g_KS[NH][D_];

__device__ __forceinline__ float fmap(float x) {      // elu(x)+1
    return x > 0.f ? x + 1.f : __expf(x);
}
__device__ __forceinline__ float totf32(float x) {    // round-to-nearest tf32
    uint32_t u;
    asm("cvt.rna.tf32.f32 %0, %1;" : "=r"(u) : "f"(x));
    return __uint_as_float(u);
}
__device__ __forceinline__ float ffrag(float x) { return totf32(fmap(x)); }

__device__ __forceinline__ void cp16(void* smem_dst, const void* gmem_src) {
    uint32_t d = (uint32_t)__cvta_generic_to_shared(smem_dst);
    asm volatile("cp.async.cg.shared.global [%0], [%1], 16;\n" :: "r"(d), "l"(gmem_src));
}
__device__ __forceinline__ void cp_commit() {
    asm volatile("cp.async.commit_group;\n");
}
template <int N>
__device__ __forceinline__ void cp_wait() {
    asm volatile("cp.async.wait_group %0;\n" :: "n"(N));
}

__device__ __forceinline__ void mma_tf32(float* c,
                                         uint32_t a0, uint32_t a1, uint32_t a2, uint32_t a3,
                                         uint32_t b0, uint32_t b1) {
    asm volatile("mma.sync.aligned.m16n8k8.row.col.f32.tf32.tf32.f32 "
                 "{%0,%1,%2,%3}, {%4,%5,%6,%7}, {%8,%9}, {%0,%1,%2,%3};\n"
                 : "+f"(c[0]), "+f"(c[1]), "+f"(c[2]), "+f"(c[3])
                 : "r"(a0), "r"(a1), "r"(a2), "r"(a3), "r"(b0), "r"(b1));
}

// ───────────────────────── Pass 1: KV[d][m] = Σ_l f(k)[l,d]·v[l,m], Ksum[d] = Σ_l f(k)[l,d]
// Grid (NH, 32), 128 threads / 4 warps. Warp w owns a 32x32 quadrant:
//   d0 = (w&1)*32, c0 = (w>>1)*32, acc[2][4][4].
// Per kk-step: 8 A loads + 8 B loads feed 8 MMAs (fragments reused both ways).
struct P1Smem {
    float ks[2][P1_T][STR];
    float vs[2][P1_T][STR];
};
#define SMEM1 ((int)sizeof(P1Smem))

__global__ __launch_bounds__(128) void pass1(const float* __restrict__ keys,
                                             const float* __restrict__ values) {
    extern __shared__ char smraw[];
    P1Smem& sm = *reinterpret_cast<P1Smem*>(smraw);

    const int nh = blockIdx.x, chunk = blockIdx.y;
    const int n = nh >> 3, h = nh & 7;
    const int tid = threadIdx.x;
    const int w = tid >> 5, lane = tid & 31;
    const int gid = lane >> 2, tig = lane & 3;
    const int d0 = (w & 1) * 32;
    const int c0 = (w >> 1) * 32;

    const float* kb = keys   + ((size_t)(n * L_) * H_ + h) * D_;
    const float* vb = values + ((size_t)(n * L_) * H_ + h) * D_;
    const int l0 = chunk * P1_LC;

    auto issue = [&](int it) {
        const int b = it & 1;
        const int lb = l0 + it * P1_T;
        #pragma unroll
        for (int i = 0; i < 4; ++i) {
            int f = i * 128 + tid;
            int t = f >> 4, c4 = (f & 15) * 4;
            size_t row = (size_t)(lb + t) * (H_ * D_);
            cp16(&sm.ks[b][t][c4], kb + row + c4);
            cp16(&sm.vs[b][t][c4], vb + row + c4);
        }
        cp_commit();
    };

    float acc[2][4][4] = {};
    float s_lo[2] = {0.f, 0.f}, s_hi[2] = {0.f, 0.f};

    issue(0);
    #pragma unroll
    for (int it = 0; it < P1_NT; ++it) {
        if (it + 1 < P1_NT) { issue(it + 1); cp_wait<1>(); }
        else                { cp_wait<0>(); }
        __syncthreads();

        const float (*ksb)[STR] = sm.ks[it & 1];
        const float (*vsb)[STR] = sm.vs[it & 1];

        #pragma unroll
        for (int kk = 0; kk < P1_T; kk += 8) {
            uint32_t a[2][4];
            #pragma unroll
            for (int di = 0; di < 2; ++di) {
                int dr = d0 + di * 16;
                float a0f = ffrag(ksb[kk + tig    ][dr + gid    ]);
                float a1f = ffrag(ksb[kk + tig    ][dr + gid + 8]);
                float a2f = ffrag(ksb[kk + tig + 4][dr + gid    ]);
                float a3f = ffrag(ksb[kk + tig + 4][dr + gid + 8]);
                s_lo[di] += a0f + a2f;
                s_hi[di] += a1f + a3f;
                a[di][0] = __float_as_uint(a0f); a[di][1] = __float_as_uint(a1f);
                a[di][2] = __float_as_uint(a2f); a[di][3] = __float_as_uint(a3f);
            }
            #pragma unroll
            for (int j = 0; j < 4; ++j) {
                uint32_t b0 = __float_as_uint(totf32(vsb[kk + tig    ][c0 + j * 8 + gid]));
                uint32_t b1 = __float_as_uint(totf32(vsb[kk + tig + 4][c0 + j * 8 + gid]));
                mma_tf32(acc[0][j], a[0][0], a[0][1], a[0][2], a[0][3], b0, b1);
                mma_tf32(acc[1][j], a[1][0], a[1][1], a[1][2], a[1][3], b0, b1);
            }
        }
        __syncthreads();
    }

    // Ksum: reduce over tig lanes (disjoint l); only c0==0 warps (w0: d 0..31, w1: d 32..63) store.
    #pragma unroll
    for (int di = 0; di < 2; ++di) {
        s_lo[di] += __shfl_xor_sync(0xffffffffu, s_lo[di], 1);
        s_lo[di] += __shfl_xor_sync(0xffffffffu, s_lo[di], 2);
        s_hi[di] += __shfl_xor_sync(0xffffffffu, s_hi[di], 1);
        s_hi[di] += __shfl_xor_sync(0xffffffffu, s_hi[di], 2);
    }
    if (c0 == 0 && tig == 0) {
        #pragma unroll
        for (int di = 0; di < 2; ++di) {
            g_KSp[nh][chunk][d0 + di * 16 + gid]     = s_lo[di];
            g_KSp[nh][chunk][d0 + di * 16 + gid + 8] = s_hi[di];
        }
    }
    float* kv = g_KVp[nh][chunk];
    #pragma unroll
    for (int di = 0; di < 2; ++di) {
        int dr = d0 + di * 16;
        #pragma unroll
        for (int j = 0; j < 4; ++j) {
            int col = c0 + j * 8 + tig * 2;
            *(float2*)&kv[(dr + gid    ) * D_ + col] = make_float2(acc[di][j][0], acc[di][j][1]);
            *(float2*)&kv[(dr + gid + 8) * D_ + col] = make_float2(acc[di][j][2], acc[di][j][3]);
        }
    }
}

// ───────────────────────── Reduce: sum 32 partials; pre-convert KV to tf32 for pass2
__global__ __launch_bounds__(256) void reduce_kernel() {
    if (blockIdx.x < 128) {
        int base = blockIdx.x * 256 + threadIdx.x;   // float4 index into [NH][4096]
        int nh = base >> 10;
        int e  = base & 1023;
        float4 s = make_float4(0.f, 0.f, 0.f, 0.f);
        #pragma unroll 8
        for (int p = 0; p < NPART; ++p) {
            float4 v = ((const float4*)g_KVp[nh][p])[e];
            s.x += v.x; s.y += v.y; s.z += v.z; s.w += v.w;
        }
        s.x = totf32(s.x); s.y = totf32(s.y); s.z = totf32(s.z); s.w = totf32(s.w);
        ((float4*)g_KV[nh])[e] = s;
    } else {
        for (int i = threadIdx.x; i < NH * D_ / 4; i += 256) {
            int nh = i >> 4;
            int e  = i & 15;
            float4 s = make_float4(0.f, 0.f, 0.f, 0.f);
            #pragma unroll 8
            for (int p = 0; p < NPART; ++p) {
                float4 v = ((const float4*)g_KSp[nh][p])[e];
                s.x += v.x; s.y += v.y; s.z += v.z; s.w += v.w;
            }
            ((float4*)g_KS[nh])[e] = s;
        }
    }
}

// ───────────────────────── Pass 2 (R6 verbatim): out[l][m] = z_l · Σ_d f(q)[l,d]·KV[d][m]
// Grid (NH, 32), 512 threads. cp.async burst; q fmapped at fragment read.
struct P2Smem {
    float kv[D_][STR];
    float q[TL2][STR];
    float ks[D_];
};
#define SMEM2 ((int)sizeof(P2Smem))

__global__ __launch_bounds__(512) void pass2(const float* __restrict__ queries,
                                             float* __restrict__ out) {
    extern __shared__ char smraw[];
    P2Smem& sm = *reinterpret_cast<P2Smem*>(smraw);

    const int nh = blockIdx.x, tile = blockIdx.y;
    const int n = nh >> 3, h = nh & 7;
    const int tid = threadIdx.x;
    const int w = tid >> 5, lane = tid & 31;
    const int gid = lane >> 2, tig = lane & 3;
    const int l0 = tile * TL2;

    // q tile first (DRAM): 2048 16B chunks over 512 threads
    const float* qb = queries + ((size_t)(n * L_) * H_ + h) * D_;
    #pragma unroll
    for (int r = 0; r < 4; ++r) {
        int f = r * 512 + tid;
        int t = f >> 4, q4 = (f & 15) * 4;
        cp16(&sm.q[t][q4], qb + (size_t)(l0 + t) * (H_ * D_) + q4);
    }
    // KV tile (L2-resident, already tf32): 1024 chunks
    #pragma unroll
    for (int r = 0; r < 2; ++r) {
        int f = r * 512 + tid;
        int dd = f >> 4, q4 = (f & 15) * 4;
        cp16(&sm.kv[dd][q4], (const char*)g_KV[nh] + (size_t)f * 16);
    }
    if (tid < D_) sm.ks[tid] = g_KS[nh][tid];
    cp_commit();
    cp_wait<0>();
    __syncthreads();

    const int lb = (w >> 1) * 16;
    const int c0 = (w & 1) * 32;
    float acc[4][4] = {};
    float s_lo = 0.f, s_hi = 0.f;

    #pragma unroll
    for (int kk = 0; kk < D_; kk += 8) {
        float ka = sm.ks[kk + tig], kc = sm.ks[kk + tig + 4];
        float a0f = ffrag(sm.q[lb + gid    ][kk + tig    ]);
        float a1f = ffrag(sm.q[lb + gid + 8][kk + tig    ]);
        float a2f = ffrag(sm.q[lb + gid    ][kk + tig + 4]);
        float a3f = ffrag(sm.q[lb + gid + 8][kk + tig + 4]);
        s_lo += a0f * ka + a2f * kc;
        s_hi += a1f * ka + a3f * kc;
        uint32_t a0 = __float_as_uint(a0f), a1 = __float_as_uint(a1f);
        uint32_t a2 = __float_as_uint(a2f), a3 = __float_as_uint(a3f);
        #pragma unroll
        for (int j = 0; j < 4; ++j) {
            uint32_t b0 = __float_as_uint(sm.kv[kk + tig    ][c0 + j * 8 + gid]);
            uint32_t b1 = __float_as_uint(sm.kv[kk + tig + 4][c0 + j * 8 + gid]);
            mma_tf32(acc[j], a0, a1, a2, a3, b0, b1);
        }
    }

    s_lo += __shfl_xor_sync(0xffffffffu, s_lo, 1);
    s_lo += __shfl_xor_sync(0xffffffffu, s_lo, 2);
    s_hi += __shfl_xor_sync(0xffffffffu, s_hi, 1);
    s_hi += __shfl_xor_sync(0xffffffffu, s_hi, 2);
    const float z_lo = 1.f / (s_lo + EPSF);
    const float z_hi = 1.f / (s_hi + EPSF);

    float* ob_lo = out + (((size_t)(n * L_) + l0 + lb + gid    ) * H_ + h) * D_ + c0;
    float* ob_hi = out + (((size_t)(n * L_) + l0 + lb + gid + 8) * H_ + h) * D_ + c0;
    #pragma unroll
    for (int j = 0; j < 4; ++j) {
        int col = j * 8 + tig * 2;
        *(float2*)(ob_lo + col) = make_float2(acc[j][0] * z_lo, acc[j][1] * z_lo);
        *(float2*)(ob_hi + col) = make_float2(acc[j][2] * z_hi, acc[j][3] * z_hi);
    }
}

extern "C" void kernel_launch(void* const* d_in, const int* in_sizes, int n_in,
                              void* d_out, int out_size) {
    const float* q = (const float*)d_in[0];
    const float* k = (const float*)d_in[1];
    const float* v = (const float*)d_in[2];
    float* out = (float*)d_out;
    (void)in_sizes; (void)n_in; (void)out_size;

    // Idempotent, not stream ops — safe under graph capture.
    cudaFuncSetAttribute(pass1, cudaFuncAttributeMaxDynamicSharedMemorySize, SMEM1);
    cudaFuncSetAttribute(pass2, cudaFuncAttributeMaxDynamicSharedMemorySize, SMEM2);

    pass1<<<dim3(NH, P1_CHUNKS), 128, SMEM1>>>(k, v);
    reduce_kernel<<<129, 256>>>();
    pass2<<<dim3(NH, L_ / TL2), 512, SMEM2>>>(q, out);
}